// round 4
// baseline (speedup 1.0000x reference)
#include <cuda_runtime.h>
#include <cuda_bf16.h>

#define IN_F   4096
#define OUT_F  4098
#define BATCH  2048
#define TOTAL  (BATCH * OUT_F)

// Per-column folded coefficients: out[b,j] = c0[j]*x[b,j] + c1[j]*x[b,j-1] + c2[j]*x[b,j-2]
// (invalid taps have coefficient exactly 0, so clamped x-loads are harmless)
__device__ float4 g_coeff[OUT_F];

__global__ __launch_bounds__(256)
void coeff_kernel(const float* __restrict__ weight, const float* __restrict__ bias) {
    int j = blockIdx.x * blockDim.x + threadIdx.x;
    if (j >= OUT_F) return;
    float m = 1.0f + bias[j];
    int n_hi = min(j, IN_F - 1);          // last scan step touching column j
    float c[3];
#pragma unroll
    for (int k = 0; k < 3; ++k) {
        int n = j - k;                    // scan step contributing via tap k
        float v = 0.0f;
        if (n >= 0 && n < IN_F) {
            int p = n_hi - n + 1;         // number of multiplies applied after this add (1..3)
            float mp = m;
            if (p >= 2) mp *= m;
            if (p >= 3) mp *= m;
            v = weight[(size_t)j * IN_F + n] * mp;
        }
        c[k] = v;
    }
    g_coeff[j] = make_float4(c[0], c[1], c[2], 0.0f);
}

__global__ __launch_bounds__(256)
void spread_kernel(const float* __restrict__ x, float* __restrict__ out) {
    int t = blockIdx.x * blockDim.x + threadIdx.x;
    if (t >= TOTAL / 2) return;
    // Each thread produces 2 consecutive outputs (row length 4098 is even, so a
    // pair never straddles a row; float2 store is 8B-aligned).
    int b = t / (OUT_F / 2);
    int j = (t - b * (OUT_F / 2)) * 2;    // even

    const float* xr = x + (size_t)b * IN_F;
    float4 c0 = g_coeff[j];
    float4 c1 = g_coeff[j + 1];

    float o0, o1;
    if (j >= 2 && j + 1 < IN_F) {
        // interior fast path: x[j-2..j+1] all valid, two aligned float2 loads
        float2 a  = *reinterpret_cast<const float2*>(xr + j - 2);  // x[j-2], x[j-1]
        float2 bb = *reinterpret_cast<const float2*>(xr + j);      // x[j],   x[j+1]
        o0 = c0.x * bb.x + c0.y * a.y  + c0.z * a.x;
        o1 = c1.x * bb.y + c1.y * bb.x + c1.z * a.y;
    } else {
        // boundary pairs (j==0 or j>=4096): clamped scalar loads, zero coeffs
        // guarantee correctness.
        int p0 = min(j, IN_F - 1);
        int p1 = min(max(j - 1, 0), IN_F - 1);
        int p2 = max(j - 2, 0);
        int q0 = min(j + 1, IN_F - 1);
        int q1 = min(j, IN_F - 1);
        int q2 = max(j - 1, 0);
        o0 = c0.x * xr[p0] + c0.y * xr[p1] + c0.z * xr[p2];
        o1 = c1.x * xr[q0] + c1.y * xr[q1] + c1.z * xr[q2];
    }
    *reinterpret_cast<float2*>(out + (size_t)b * OUT_F + j) = make_float2(o0, o1);
}

extern "C" void kernel_launch(void* const* d_in, const int* in_sizes, int n_in,
                              void* d_out, int out_size) {
    const float* x      = (const float*)d_in[0];
    const float* weight = (const float*)d_in[1];
    const float* bias   = (const float*)d_in[2];
    float* out = (float*)d_out;

    coeff_kernel<<<(OUT_F + 255) / 256, 256>>>(weight, bias);
    spread_kernel<<<(TOTAL / 2 + 255) / 256, 256>>>(x, out);
}

// round 8
// speedup vs baseline: 1.1150x; 1.1150x over previous
#include <cuda_runtime.h>
#include <cuda_bf16.h>

#define IN_F   4096
#define OUT_F  4098
#define BATCH  2048
#define QUADS  1025          // ceil(OUT_F/4); last quad has 2 valid columns
#define ROWS_PER_BLK 16      // rows each thread iterates (gridDim.y = BATCH/ROWS_PER_BLK)

// Per-column folded coefficients: out[b,j] = c0[j]*x[b,j] + c1[j]*x[b,j-1] + c2[j]*x[b,j-2]
// (invalid taps have coefficient exactly 0)
__device__ float4 g_coeff[OUT_F + 2];   // +2 pad so quad loads at j=4096 stay in bounds

__global__ __launch_bounds__(256)
void coeff_kernel(const float* __restrict__ weight, const float* __restrict__ bias) {
    int j = blockIdx.x * blockDim.x + threadIdx.x;
    if (j >= OUT_F + 2) return;
    if (j >= OUT_F) { g_coeff[j] = make_float4(0.f, 0.f, 0.f, 0.f); return; }
    float m = 1.0f + bias[j];
    int n_hi = min(j, IN_F - 1);          // last scan step touching column j
    float c[3];
#pragma unroll
    for (int k = 0; k < 3; ++k) {
        int n = j - k;                    // scan step contributing via tap k
        float v = 0.0f;
        if (n >= 0 && n < IN_F) {
            int p = n_hi - n + 1;         // multiplies applied after this add (1..3)
            float mp = m;
            if (p >= 2) mp *= m;
            if (p >= 3) mp *= m;
            v = weight[(size_t)j * IN_F + n] * mp;
        }
        c[k] = v;
    }
    g_coeff[j] = make_float4(c[0], c[1], c[2], 0.0f);
}

// Thread owns columns [4q, 4q+4) and loops over ROWS_PER_BLK rows.
// Coefficients live in registers -> only x loads + out stores hit L1 per row.
__global__ __launch_bounds__(256)
void spread_kernel(const float* __restrict__ x, float* __restrict__ out) {
    int q = blockIdx.x * blockDim.x + threadIdx.x;
    if (q >= QUADS) return;
    int j = q * 4;

    // coefficient registers (loaded once, reused for all rows)
    float4 c0 = g_coeff[j];
    float4 c1 = g_coeff[j + 1];
    float4 c2 = g_coeff[j + 2];
    float4 c3 = g_coeff[j + 3];

    int b0 = blockIdx.y * ROWS_PER_BLK;
    const float* xr  = x   + (size_t)b0 * IN_F;
    float*       orw = out + (size_t)b0 * OUT_F;

    if (j >= 4 && j <= IN_F - 4) {
        // interior: x[j-2..j+3] fully inside the row
#pragma unroll 4
        for (int r = 0; r < ROWS_PER_BLK; ++r) {
            float2 a = *reinterpret_cast<const float2*>(xr + j - 2); // x[j-2],x[j-1]
            float4 v = *reinterpret_cast<const float4*>(xr + j);     // x[j..j+3]
            float2 lo, hi;
            lo.x = c0.x * v.x + c0.y * a.y + c0.z * a.x;
            lo.y = c1.x * v.y + c1.y * v.x + c1.z * a.y;
            hi.x = c2.x * v.z + c2.y * v.y + c2.z * v.x;
            hi.y = c3.x * v.w + c3.y * v.z + c3.z * v.y;
            // OUT_F row stride is 8 mod 16 bytes -> float4 store misaligned on
            // odd rows; use two 8B stores (always aligned: j even).
            *reinterpret_cast<float2*>(orw + j)     = lo;
            *reinterpret_cast<float2*>(orw + j + 2) = hi;
            xr  += IN_F;
            orw += OUT_F;
        }
    } else if (j == 0) {
        // left edge: taps into x[-2],x[-1] have zero coeffs; substitute 0
#pragma unroll 4
        for (int r = 0; r < ROWS_PER_BLK; ++r) {
            float4 v = *reinterpret_cast<const float4*>(xr);         // x[0..3]
            float2 lo, hi;
            lo.x = c0.x * v.x;                                       // c0.y=c0.z=0
            lo.y = c1.x * v.y + c1.y * v.x;                          // c1.z=0
            hi.x = c2.x * v.z + c2.y * v.y + c2.z * v.x;
            hi.y = c3.x * v.w + c3.y * v.z + c3.z * v.y;
            *reinterpret_cast<float2*>(orw)     = lo;
            *reinterpret_cast<float2*>(orw + 2) = hi;
            xr  += IN_F;
            orw += OUT_F;
        }
    } else {
        // right edge quad j=4096: only cols 4096,4097 valid; c0.x=c1.x=c1.y=0
#pragma unroll 4
        for (int r = 0; r < ROWS_PER_BLK; ++r) {
            float2 a = *reinterpret_cast<const float2*>(xr + IN_F - 2); // x[4094],x[4095]
            float2 lo;
            lo.x = c0.y * a.y + c0.z * a.x;   // col 4096
            lo.y = c1.z * a.y;                // col 4097
            *reinterpret_cast<float2*>(orw + j) = lo;
            xr  += IN_F;
            orw += OUT_F;
        }
    }
}

extern "C" void kernel_launch(void* const* d_in, const int* in_sizes, int n_in,
                              void* d_out, int out_size) {
    const float* x      = (const float*)d_in[0];
    const float* weight = (const float*)d_in[1];
    const float* bias   = (const float*)d_in[2];
    float* out = (float*)d_out;

    coeff_kernel<<<(OUT_F + 2 + 255) / 256, 256>>>(weight, bias);

    dim3 grid((QUADS + 255) / 256, BATCH / ROWS_PER_BLK);
    spread_kernel<<<grid, 256>>>(x, out);
}

// round 11
// speedup vs baseline: 1.1378x; 1.0204x over previous
#include <cuda_runtime.h>
#include <cuda_bf16.h>

#define IN_F   4096
#define OUT_F  4098
#define BATCH  2048
#define QUADS  1025          // ceil(OUT_F/4); last quad has 2 valid columns
#define ROWS_PER_BLK 4       // rows each thread handles (fully unrolled)

// Per-column folded coefficients: out[b,j] = c0[j]*x[b,j] + c1[j]*x[b,j-1] + c2[j]*x[b,j-2]
// (invalid taps have coefficient exactly 0)
__device__ float4 g_coeff[OUT_F + 2];   // +2 pad so quad loads at j=4096 stay in bounds

__global__ __launch_bounds__(256)
void coeff_kernel(const float* __restrict__ weight, const float* __restrict__ bias) {
    int j = blockIdx.x * blockDim.x + threadIdx.x;
    if (j >= OUT_F + 2) return;
    if (j >= OUT_F) { g_coeff[j] = make_float4(0.f, 0.f, 0.f, 0.f); return; }
    float m = 1.0f + bias[j];
    int n_hi = min(j, IN_F - 1);          // last scan step touching column j
    float c[3];
#pragma unroll
    for (int k = 0; k < 3; ++k) {
        int n = j - k;                    // scan step contributing via tap k
        float v = 0.0f;
        if (n >= 0 && n < IN_F) {
            int p = n_hi - n + 1;         // multiplies applied after this add (1..3)
            float mp = m;
            if (p >= 2) mp *= m;
            if (p >= 3) mp *= m;
            v = weight[(size_t)j * IN_F + n] * mp;
        }
        c[k] = v;
    }
    g_coeff[j] = make_float4(c[0], c[1], c[2], 0.0f);
}

// Thread owns columns [4q, 4q+4) for 4 rows (fully unrolled, loads batched).
__global__ __launch_bounds__(256)
void spread_kernel(const float* __restrict__ x, float* __restrict__ out) {
    int q = blockIdx.x * blockDim.x + threadIdx.x;
    if (q >= QUADS) return;
    int j = q * 4;

    int b0 = blockIdx.y * ROWS_PER_BLK;
    const float* xr  = x   + (size_t)b0 * IN_F;
    float*       orw = out + (size_t)b0 * OUT_F;

    // coefficient registers (one LDG.128 x4, amortized over 4 rows, L1/L2-hot)
    float4 c0 = g_coeff[j];
    float4 c1 = g_coeff[j + 1];
    float4 c2 = g_coeff[j + 2];
    float4 c3 = g_coeff[j + 3];

    if (j >= 4 && j <= IN_F - 4) {
        // interior: batch all 8 loads first (MLP=8), then compute+store
        float2 a[ROWS_PER_BLK];
        float4 v[ROWS_PER_BLK];
#pragma unroll
        for (int r = 0; r < ROWS_PER_BLK; ++r) {
            const float* p = xr + (size_t)r * IN_F;
            a[r] = *reinterpret_cast<const float2*>(p + j - 2); // x[j-2],x[j-1]
            v[r] = *reinterpret_cast<const float4*>(p + j);     // x[j..j+3]
        }
#pragma unroll
        for (int r = 0; r < ROWS_PER_BLK; ++r) {
            float2 lo, hi;
            lo.x = c0.x * v[r].x + c0.y * a[r].y + c0.z * a[r].x;
            lo.y = c1.x * v[r].y + c1.y * v[r].x + c1.z * a[r].y;
            hi.x = c2.x * v[r].z + c2.y * v[r].y + c2.z * v[r].x;
            hi.y = c3.x * v[r].w + c3.y * v[r].z + c3.z * v[r].y;
            float* po = orw + (size_t)r * OUT_F;
            // OUT_F stride is 8 mod 16 bytes -> float4 store misaligned on odd
            // rows; two 8B stores are always aligned (j even).
            *reinterpret_cast<float2*>(po + j)     = lo;
            *reinterpret_cast<float2*>(po + j + 2) = hi;
        }
    } else if (j == 0) {
        // left edge: taps into x[-2],x[-1] have zero coeffs
        float4 v[ROWS_PER_BLK];
#pragma unroll
        for (int r = 0; r < ROWS_PER_BLK; ++r)
            v[r] = *reinterpret_cast<const float4*>(xr + (size_t)r * IN_F);
#pragma unroll
        for (int r = 0; r < ROWS_PER_BLK; ++r) {
            float2 lo, hi;
            lo.x = c0.x * v[r].x;                               // c0.y=c0.z=0
            lo.y = c1.x * v[r].y + c1.y * v[r].x;               // c1.z=0
            hi.x = c2.x * v[r].z + c2.y * v[r].y + c2.z * v[r].x;
            hi.y = c3.x * v[r].w + c3.y * v[r].z + c3.z * v[r].y;
            float* po = orw + (size_t)r * OUT_F;
            *reinterpret_cast<float2*>(po)     = lo;
            *reinterpret_cast<float2*>(po + 2) = hi;
        }
    } else {
        // right edge quad j=4096: only cols 4096,4097 valid; c0.x=c1.x=c1.y=0
        float2 a[ROWS_PER_BLK];
#pragma unroll
        for (int r = 0; r < ROWS_PER_BLK; ++r)
            a[r] = *reinterpret_cast<const float2*>(xr + (size_t)r * IN_F + IN_F - 2);
#pragma unroll
        for (int r = 0; r < ROWS_PER_BLK; ++r) {
            float2 lo;
            lo.x = c0.y * a[r].y + c0.z * a[r].x;   // col 4096
            lo.y = c1.z * a[r].y;                   // col 4097
            *reinterpret_cast<float2*>(orw + (size_t)r * OUT_F + j) = lo;
        }
    }
}

extern "C" void kernel_launch(void* const* d_in, const int* in_sizes, int n_in,
                              void* d_out, int out_size) {
    const float* x      = (const float*)d_in[0];
    const float* weight = (const float*)d_in[1];
    const float* bias   = (const float*)d_in[2];
    float* out = (float*)d_out;

    coeff_kernel<<<(OUT_F + 2 + 255) / 256, 256>>>(weight, bias);

    dim3 grid((QUADS + 255) / 256, BATCH / ROWS_PER_BLK);
    spread_kernel<<<grid, 256>>>(x, out);
}